// round 7
// baseline (speedup 1.0000x reference)
#include <cuda_runtime.h>
#include <cuda_bf16.h>
#include <math.h>
#include <stdint.h>

#define BB 128
#define PP 196
#define EE 2048
#define HH 512
#define VV 10000
#define VPAD 10112
#define TT 20
#define SS 19
#define XK 3072
#define G4 2048

typedef __nv_bfloat16 bf16;

// ---------------- device global scratch ----------------
__device__ bf16  g_imgh[(size_t)BB * PP * EE];
__device__ bf16  g_imgl[(size_t)BB * PP * EE];
__device__ float g_Ws[(size_t)BB * PP * HH];
__device__ bf16  g_BWatt_h[HH * EE],  g_BWatt_l[HH * EE];
__device__ bf16  g_BWih_h[HH * EE],   g_BWih_l[HH * EE];
__device__ bf16  g_BWic_h[HH * EE],   g_BWic_l[HH * EE];
__device__ bf16  g_BUatt_h[HH * HH],  g_BUatt_l[HH * HH];
__device__ bf16  g_BWfb_h[EE * HH],   g_BWfb_l[EE * HH];
__device__ bf16  g_BWcat_h[(size_t)G4 * XK], g_BWcat_l[(size_t)G4 * XK];
__device__ bf16  g_BWdo_h[(size_t)VPAD * HH], g_BWdo_l[(size_t)VPAD * HH];
__device__ bf16  g_avgh[BB * EE], g_avgl[BB * EE];
__device__ bf16  g_Xh[BB * XK],   g_Xl[BB * XK];
__device__ float g_avg[BB * EE];
__device__ float g_c[BB * HH];
__device__ float g_alpha[BB * PP];
// split-K partial buffers (fp32). g_gatep doubles as h0 partials (8*BB*HH fits),
// g_gatesp doubles as c0 partials.
__device__ float g_qp[4 * BB * HH];
__device__ float g_gatep[4 * BB * EE];
__device__ float g_gatesp[3 * BB * G4];

// ---------------- helpers ----------------
__device__ __forceinline__ uint32_t s2u(const void* p) {
    uint32_t a;
    asm("{ .reg .u64 t; cvta.to.shared.u64 t, %1; cvt.u32.u64 %0, t; }" : "=r"(a) : "l"(p));
    return a;
}
__device__ __forceinline__ void cp16(uint32_t s, const void* g) {
    asm volatile("cp.async.cg.shared.global [%0], [%1], 16;" :: "r"(s), "l"(g) : "memory");
}
__device__ __forceinline__ void cp_commit() { asm volatile("cp.async.commit_group;" ::: "memory"); }
template <int N> __device__ __forceinline__ void cp_wait() {
    asm volatile("cp.async.wait_group %0;" :: "n"(N) : "memory");
}
__device__ __forceinline__ void ldsm4(uint32_t* r, uint32_t addr) {
    asm volatile("ldmatrix.sync.aligned.m8n8.x4.shared.b16 {%0,%1,%2,%3}, [%4];"
                 : "=r"(r[0]), "=r"(r[1]), "=r"(r[2]), "=r"(r[3]) : "r"(addr));
}
__device__ __forceinline__ void mma16816(float* d, const uint32_t* a, const uint32_t* b) {
    asm volatile("mma.sync.aligned.m16n8k16.row.col.f32.bf16.bf16.f32 "
                 "{%0,%1,%2,%3}, {%4,%5,%6,%7}, {%8,%9}, {%0,%1,%2,%3};"
                 : "+f"(d[0]), "+f"(d[1]), "+f"(d[2]), "+f"(d[3])
                 : "r"(a[0]), "r"(a[1]), "r"(a[2]), "r"(a[3]), "r"(b[0]), "r"(b[1]));
}
__device__ __forceinline__ float ex2f(float x) { float r; asm("ex2.approx.f32 %0,%1;" : "=f"(r) : "f"(x)); return r; }
__device__ __forceinline__ float rcpf(float x) { float r; asm("rcp.approx.f32 %0,%1;" : "=f"(r) : "f"(x)); return r; }
__device__ __forceinline__ float tanh_fast(float x) {
    float ax = fabsf(x);
    float e  = ex2f(ax * -2.8853900817779268f);
    float r  = (1.0f - e) * rcpf(1.0f + e);
    return copysignf(r, x);
}
__device__ __forceinline__ void split2(float v, bf16* ph, bf16* pl) {
    bf16 h = __float2bfloat16(v);
    *ph = h;
    *pl = __float2bfloat16(v - __bfloat162float(h));
}

// ---------------- split-bf16 HMMA GEMM, 4-stage pipeline, split-K via grid.z ----
// C[z][M,Nstore] = (A @ B^T) [+ bias if non-null], K-range z*(K/Z)..(z+1)*(K/Z)
// A: (Ah,Al)[M,K] bf16 stride lda.  B: (Bh,Bl)[Npad,K] bf16 stride K.
// CTA tile 128x128, BK=32, 8 warps (2M x 4N), warp tile 64x32.
#define TILE_B   10240          // 128 * 80
#define BUF_B    40960          // 4 tiles (Ah,Al,Bh,Bl)
#define SMEM_SZ  163840         // 4 stages

__global__ void __launch_bounds__(256, 1)
tc_gemm(const bf16* __restrict__ Ah, const bf16* __restrict__ Al, int lda,
        const bf16* __restrict__ Bh, const bf16* __restrict__ Bl,
        const float* __restrict__ bias, float* __restrict__ C, int ldc,
        int Nstore, int K)
{
    extern __shared__ char sm[];
    const int tid = threadIdx.x, lane = tid & 31, wid = tid >> 5;
    const int m0 = blockIdx.y << 7, n0 = blockIdx.x << 7;
    const int wy = wid & 1, wx = wid >> 1;
    const uint32_t sb = s2u(sm);

    const int kc = K / gridDim.z;            // this CTA's K extent
    const size_t kofs = (size_t)blockIdx.z * kc * 2;   // bytes
    C += (size_t)blockIdx.z * gridDim.y * 128 * ldc;

    const char* gAh = (const char*)(Ah + (size_t)m0 * lda) + kofs;
    const char* gAl = (const char*)(Al + (size_t)m0 * lda) + kofs;
    const char* gBh = (const char*)(Bh + (size_t)n0 * K) + kofs;
    const char* gBl = (const char*)(Bl + (size_t)n0 * K) + kofs;
    const size_t strA = (size_t)lda * 2, strB = (size_t)K * 2;

    const int arow = lane & 15;
    const int acol = (lane >> 4) << 4;
    const int brow = ((lane >> 4) << 3) + (lane & 7);
    const int bcol = ((lane >> 3) & 1) << 4;
    const uint32_t aoff = (uint32_t)((wy * 64 + arow) * 80 + acol);
    const uint32_t boff = (uint32_t)((wx * 32 + brow) * 80 + bcol);

    float acc[4][4][4] = {};
    const int nk = kc >> 5;

    auto issue = [&](int ch) {
        if (ch < nk) {
            const int k0b = ch << 6;
            const uint32_t s0 = sb + (ch & 3) * BUF_B;
            #pragma unroll
            for (int half = 0; half < 2; half++) {
                int u  = tid + half * 256;
                int r  = u >> 2;
                int sg = (u & 3) << 4;
                uint32_t s = s0 + r * 80 + sg;
                size_t gA = (size_t)r * strA + k0b + sg;
                size_t gB = (size_t)r * strB + k0b + sg;
                cp16(s,              gAh + gA);
                cp16(s + TILE_B,     gAl + gA);
                cp16(s + 2 * TILE_B, gBh + gB);
                cp16(s + 3 * TILE_B, gBl + gB);
            }
        }
        cp_commit();   // empty groups at tail keep wait_group counts valid
    };

    issue(0); issue(1); issue(2);

    for (int ch = 0; ch < nk; ch++) {
        cp_wait<2>();            // chunks ch+1, ch+2 may remain in flight
        __syncthreads();         // all reads of buffer (ch+3)&3 from iter ch-1 done
        issue(ch + 3);           // overlap next load with this chunk's compute

        const uint32_t base = sb + (ch & 3) * BUF_B;
        #pragma unroll
        for (int ks = 0; ks < 2; ks++) {
            uint32_t ah[4][4], al[4][4];
            #pragma unroll
            for (int mi = 0; mi < 4; mi++) {
                uint32_t o = aoff + mi * (16 * 80) + ks * 32;
                ldsm4(ah[mi], base + o);
                ldsm4(al[mi], base + TILE_B + o);
            }
            uint32_t bh[2][4], bl[2][4];
            #pragma unroll
            for (int nj = 0; nj < 2; nj++) {
                uint32_t o = boff + nj * (16 * 80) + ks * 32;
                ldsm4(bh[nj], base + 2 * TILE_B + o);
                ldsm4(bl[nj], base + 3 * TILE_B + o);
            }
            #pragma unroll
            for (int mi = 0; mi < 4; mi++) {
                #pragma unroll
                for (int n8 = 0; n8 < 4; n8++) {
                    const uint32_t* pbh = &bh[n8 >> 1][(n8 & 1) << 1];
                    const uint32_t* pbl = &bl[n8 >> 1][(n8 & 1) << 1];
                    mma16816(acc[mi][n8], ah[mi], pbh);
                    mma16816(acc[mi][n8], ah[mi], pbl);
                    mma16816(acc[mi][n8], al[mi], pbh);
                }
            }
        }
    }

    #pragma unroll
    for (int mi = 0; mi < 4; mi++) {
        #pragma unroll
        for (int n8 = 0; n8 < 4; n8++) {
            int mb = m0 + wy * 64 + mi * 16 + (lane >> 2);
            int nb = n0 + wx * 32 + n8 * 8 + ((lane & 3) << 1);
            #pragma unroll
            for (int g = 0; g < 2; g++) {
                int m = mb + g * 8;
                #pragma unroll
                for (int j = 0; j < 2; j++) {
                    int n = nb + j;
                    if (n < Nstore) {
                        float v = acc[mi][n8][g * 2 + j];
                        if (bias) v += bias[n];
                        C[(size_t)m * ldc + n] = v;
                    }
                }
            }
        }
    }
}

// ---------------- conversion kernels ----------------
__global__ void split_kernel(const float* __restrict__ src, bf16* __restrict__ dh,
                             bf16* __restrict__ dl, int n)
{
    int i = blockIdx.x * 256 + threadIdx.x;
    if (i < n) split2(src[i], dh + i, dl + i);
}

__global__ void tsplit_kernel(const float* __restrict__ src, bf16* __restrict__ dh,
                              bf16* __restrict__ dl, int Ksrc, int N, int dst_ld, int koff)
{
    __shared__ float t[32][33];
    const int n0 = blockIdx.x << 5, k0 = blockIdx.y << 5;
    #pragma unroll
    for (int j = 0; j < 4; j++) {
        int kk = k0 + threadIdx.y + (j << 3);
        int n  = n0 + threadIdx.x;
        t[threadIdx.y + (j << 3)][threadIdx.x] = (n < N) ? src[(size_t)kk * N + n] : 0.0f;
    }
    __syncthreads();
    #pragma unroll
    for (int j = 0; j < 4; j++) {
        int nn = n0 + threadIdx.y + (j << 3);
        int k  = k0 + threadIdx.x;
        size_t o = (size_t)nn * dst_ld + koff + k;
        split2(t[threadIdx.x][threadIdx.y + (j << 3)], dh + o, dl + o);
    }
}

// ---------------- pointwise / attention kernels ----------------
__global__ void avg_kernel(const float* __restrict__ img, float* __restrict__ avg,
                           bf16* __restrict__ ah, bf16* __restrict__ al)
{
    int b = blockIdx.y;
    int e = blockIdx.x * 256 + threadIdx.x;
    const float* ib = img + (size_t)b * PP * EE + e;
    float s = 0;
    #pragma unroll 4
    for (int p = 0; p < PP; p++) s += ib[(size_t)p * EE];
    float v = s * (1.0f / PP);
    avg[b * EE + e] = v;
    split2(v, ah + b * EE + e, al + b * EE + e);
}

// sum 8 partials each for h0/c0, tanh, write c and X h-slice
__global__ void combine_init(const float* __restrict__ hp, const float* __restrict__ cp,
                             const float* __restrict__ bih, const float* __restrict__ bic,
                             float* __restrict__ c, bf16* __restrict__ Xh, bf16* __restrict__ Xl)
{
    int i = blockIdx.x * 256 + threadIdx.x;   // B*H
    int b = i >> 9, h = i & 511;
    float sh = bih[h], sc = bic[h];
    #pragma unroll
    for (int z = 0; z < 8; z++) { sh += hp[z * BB * HH + i]; sc += cp[z * BB * HH + i]; }
    c[i] = tanhf(sc);
    size_t o = (size_t)b * XK + 2560 + h;
    split2(tanhf(sh), Xh + o, Xl + o);
}

__global__ void __launch_bounds__(256)
attention_kernel(const float* __restrict__ Ws, const float* __restrict__ qp,
                 const float* __restrict__ bU,
                 const float* __restrict__ v_att, const float* __restrict__ bv,
                 float* __restrict__ alpha, float* __restrict__ alpha_out)
{
    __shared__ float qs[HH], vs[HH], es[PP], red[8];
    const int b = blockIdx.x, tid = threadIdx.x;
    const int lane = tid & 31, warp = tid >> 5;

    for (int i = tid; i < HH; i += 256) {
        float s = bU[i];
        #pragma unroll
        for (int z = 0; z < 4; z++) s += qp[z * BB * HH + b * HH + i];
        qs[i] = s;
        vs[i] = v_att[i];
    }
    __syncthreads();

    const float* Wb = Ws + (size_t)b * PP * HH;
    const float bv0 = bv[0];
    for (int p = warp; p < PP; p += 8) {
        const float* row = Wb + (size_t)p * HH;
        float s = 0.0f;
        #pragma unroll
        for (int i = 0; i < HH / 32; i++) {
            int h = lane + 32 * i;
            s += vs[h] * tanh_fast(row[h] + qs[h]);
        }
        #pragma unroll
        for (int o = 16; o; o >>= 1) s += __shfl_xor_sync(0xffffffffu, s, o);
        if (lane == 0) es[p] = s + bv0;
    }
    __syncthreads();

    float m = -1e30f;
    for (int p = tid; p < PP; p += 256) m = fmaxf(m, es[p]);
    #pragma unroll
    for (int o = 16; o; o >>= 1) m = fmaxf(m, __shfl_xor_sync(0xffffffffu, m, o));
    if (lane == 0) red[warp] = m;
    __syncthreads();
    if (warp == 0) {
        float t = (lane < 8) ? red[lane] : -1e30f;
        #pragma unroll
        for (int o = 4; o; o >>= 1) t = fmaxf(t, __shfl_xor_sync(0xffffffffu, t, o));
        if (lane == 0) red[0] = t;
    }
    __syncthreads();
    m = red[0];
    __syncthreads();

    float sum = 0.0f;
    for (int p = tid; p < PP; p += 256) { float ev = expf(es[p] - m); es[p] = ev; sum += ev; }
    #pragma unroll
    for (int o = 16; o; o >>= 1) sum += __shfl_xor_sync(0xffffffffu, sum, o);
    if (lane == 0) red[warp] = sum;
    __syncthreads();
    if (warp == 0) {
        float t = (lane < 8) ? red[lane] : 0.0f;
        #pragma unroll
        for (int o = 4; o; o >>= 1) t += __shfl_xor_sync(0xffffffffu, t, o);
        if (lane == 0) red[0] = t;
    }
    __syncthreads();
    float inv = 1.0f / red[0];
    for (int p = tid; p < PP; p += 256) {
        float a = es[p] * inv;
        alpha[b * PP + p] = a;
        alpha_out[(size_t)b * (SS * PP) + p] = a;
    }
}

__global__ void context_kernel(const float* __restrict__ img, const float* __restrict__ alpha,
                               const float* __restrict__ gatep, const float* __restrict__ bfb,
                               bf16* __restrict__ Xh, bf16* __restrict__ Xl)
{
    __shared__ float al[PP];
    const int b = blockIdx.y;
    const int e = blockIdx.x * 256 + threadIdx.x;
    if (threadIdx.x < PP) al[threadIdx.x] = alpha[b * PP + threadIdx.x];
    __syncthreads();
    const float* ib = img + (size_t)b * PP * EE + e;
    float s0 = 0, s1 = 0, s2 = 0, s3 = 0;
    #pragma unroll 4
    for (int p = 0; p < PP; p += 4) {
        s0 += al[p    ] * ib[(size_t)(p    ) * EE];
        s1 += al[p + 1] * ib[(size_t)(p + 1) * EE];
        s2 += al[p + 2] * ib[(size_t)(p + 2) * EE];
        s3 += al[p + 3] * ib[(size_t)(p + 3) * EE];
    }
    float gs = bfb[e];
    #pragma unroll
    for (int z = 0; z < 4; z++) gs += gatep[(size_t)z * BB * EE + b * EE + e];
    float gate = 1.0f / (1.0f + expf(-gs));
    float v = (s0 + s1 + s2 + s3) * gate;
    size_t o = (size_t)b * XK + HH + e;
    split2(v, Xh + o, Xl + o);
}

__global__ void emb_kernel(const float* __restrict__ Wemb, const int* __restrict__ cap,
                           int t, bf16* __restrict__ Xh, bf16* __restrict__ Xl)
{
    int i = blockIdx.x * 256 + threadIdx.x;
    int b = i >> 9, h = i & 511;
    int c = cap[b * TT + t];
    size_t o = (size_t)b * XK + h;
    split2(Wemb[(size_t)c * HH + h], Xh + o, Xl + o);
}

__global__ void lstm_kernel(const float* __restrict__ gatesp, const float* __restrict__ bl,
                            float* __restrict__ c, bf16* __restrict__ Xh, bf16* __restrict__ Xl)
{
    int i = blockIdx.x * 256 + threadIdx.x;
    int b = i >> 9, h = i & 511;
    float g[4];
    #pragma unroll
    for (int k = 0; k < 4; k++) {
        int j = k * HH + h;
        float s = bl[j];
        #pragma unroll
        for (int z = 0; z < 3; z++) s += gatesp[(size_t)z * BB * G4 + b * G4 + j];
        g[k] = s;
    }
    float ig = 1.0f / (1.0f + expf(-g[0]));
    float fg = 1.0f / (1.0f + expf(-g[1]));
    float gg = tanhf(g[2]);
    float og = 1.0f / (1.0f + expf(-g[3]));
    float cn = fg * c[i] + ig * gg;
    c[i] = cn;
    size_t o = (size_t)b * XK + 2560 + h;
    split2(og * tanhf(cn), Xh + o, Xl + o);
}

// ---------------- host launch ----------------
extern "C" void kernel_launch(void* const* d_in, const int* in_sizes, int n_in,
                              void* d_out, int out_size)
{
    const float* img   = (const float*)d_in[0];
    const int*   cap   = (const int*)  d_in[1];
    const float* U_att = (const float*)d_in[2];
    const float* bU    = (const float*)d_in[3];
    const float* W_att = (const float*)d_in[4];
    const float* bW    = (const float*)d_in[5];
    const float* v_att = (const float*)d_in[6];
    const float* bv    = (const float*)d_in[7];
    const float* Wih   = (const float*)d_in[8];
    const float* bih   = (const float*)d_in[9];
    const float* Wic   = (const float*)d_in[10];
    const float* bic   = (const float*)d_in[11];
    const float* Wfb   = (const float*)d_in[12];
    const float* bfb   = (const float*)d_in[13];
    const float* Wdo   = (const float*)d_in[14];
    const float* bdo   = (const float*)d_in[15];
    const float* Wemb  = (const float*)d_in[16];
    const float* Wl    = (const float*)d_in[17];
    const float* Ul    = (const float*)d_in[18];
    const float* bl    = (const float*)d_in[19];

    float* preds  = (float*)d_out;
    float* alphas = (float*)d_out + (size_t)BB * SS * VV;

    bf16 *imgh, *imgl, *BWatt_h, *BWatt_l, *BWih_h, *BWih_l, *BWic_h, *BWic_l;
    bf16 *BUatt_h, *BUatt_l, *BWfb_h, *BWfb_l, *BWcat_h, *BWcat_l, *BWdo_h, *BWdo_l;
    bf16 *avgh, *avgl, *Xh, *Xl;
    float *pWs, *pavg, *pc, *palpha, *pqp, *pgatep, *pgatesp;
    cudaGetSymbolAddress((void**)&imgh, g_imgh);     cudaGetSymbolAddress((void**)&imgl, g_imgl);
    cudaGetSymbolAddress((void**)&BWatt_h, g_BWatt_h); cudaGetSymbolAddress((void**)&BWatt_l, g_BWatt_l);
    cudaGetSymbolAddress((void**)&BWih_h, g_BWih_h); cudaGetSymbolAddress((void**)&BWih_l, g_BWih_l);
    cudaGetSymbolAddress((void**)&BWic_h, g_BWic_h); cudaGetSymbolAddress((void**)&BWic_l, g_BWic_l);
    cudaGetSymbolAddress((void**)&BUatt_h, g_BUatt_h); cudaGetSymbolAddress((void**)&BUatt_l, g_BUatt_l);
    cudaGetSymbolAddress((void**)&BWfb_h, g_BWfb_h); cudaGetSymbolAddress((void**)&BWfb_l, g_BWfb_l);
    cudaGetSymbolAddress((void**)&BWcat_h, g_BWcat_h); cudaGetSymbolAddress((void**)&BWcat_l, g_BWcat_l);
    cudaGetSymbolAddress((void**)&BWdo_h, g_BWdo_h); cudaGetSymbolAddress((void**)&BWdo_l, g_BWdo_l);
    cudaGetSymbolAddress((void**)&avgh, g_avgh);     cudaGetSymbolAddress((void**)&avgl, g_avgl);
    cudaGetSymbolAddress((void**)&Xh, g_Xh);         cudaGetSymbolAddress((void**)&Xl, g_Xl);
    cudaGetSymbolAddress((void**)&pWs, g_Ws);        cudaGetSymbolAddress((void**)&pavg, g_avg);
    cudaGetSymbolAddress((void**)&pc, g_c);          cudaGetSymbolAddress((void**)&palpha, g_alpha);
    cudaGetSymbolAddress((void**)&pqp, g_qp);
    cudaGetSymbolAddress((void**)&pgatep, g_gatep);
    cudaGetSymbolAddress((void**)&pgatesp, g_gatesp);

    cudaFuncSetAttribute(tc_gemm, cudaFuncAttributeMaxDynamicSharedMemorySize, SMEM_SZ);

    // one-time conversions
    {
        int n = BB * PP * EE;
        split_kernel<<<(n + 255) / 256, 256>>>(img, imgh, imgl, n);
        dim3 blk(32, 8);
        tsplit_kernel<<<dim3(16, 64), blk>>>(W_att, BWatt_h, BWatt_l, EE, HH, EE, 0);
        tsplit_kernel<<<dim3(16, 64), blk>>>(Wih,   BWih_h,  BWih_l,  EE, HH, EE, 0);
        tsplit_kernel<<<dim3(16, 64), blk>>>(Wic,   BWic_h,  BWic_l,  EE, HH, EE, 0);
        tsplit_kernel<<<dim3(16, 16), blk>>>(U_att, BUatt_h, BUatt_l, HH, HH, HH, 0);
        tsplit_kernel<<<dim3(64, 16), blk>>>(Wfb,   BWfb_h,  BWfb_l,  HH, EE, HH, 0);
        tsplit_kernel<<<dim3(64, 80), blk>>>(Wl,    BWcat_h, BWcat_l, 2560, G4, XK, 0);
        tsplit_kernel<<<dim3(64, 16), blk>>>(Ul,    BWcat_h, BWcat_l, HH,   G4, XK, 2560);
        tsplit_kernel<<<dim3(VPAD / 32, 16), blk>>>(Wdo, BWdo_h, BWdo_l, HH, VV, HH, 0);
    }

    // init: avg -> h0/c0 partials (split-K x8) -> combine
    avg_kernel<<<dim3(EE / 256, BB), 256>>>(img, pavg, avgh, avgl);
    tc_gemm<<<dim3(4, 1, 8), 256, SMEM_SZ>>>(avgh, avgl, EE, BWih_h, BWih_l,
                                             nullptr, pgatep, HH, HH, EE);
    tc_gemm<<<dim3(4, 1, 8), 256, SMEM_SZ>>>(avgh, avgl, EE, BWic_h, BWic_l,
                                             nullptr, pgatesp, HH, HH, EE);
    combine_init<<<(BB * HH) / 256, 256>>>(pgatep, pgatesp, bih, bic, pc, Xh, Xl);

    // W_s = img @ W_att + bW
    tc_gemm<<<dim3(4, 196, 1), 256, SMEM_SZ>>>(imgh, imgl, EE, BWatt_h, BWatt_l,
                                               bW, pWs, HH, HH, EE);

    for (int t = 0; t < SS; t++) {
        // q partials (split-K x4), summed + bU in attention
        tc_gemm<<<dim3(4, 1, 4), 256, SMEM_SZ>>>(Xh + 2560, Xl + 2560, XK,
                                                 BUatt_h, BUatt_l, nullptr, pqp, HH, HH, HH);
        attention_kernel<<<BB, 256>>>(pWs, pqp, bU, v_att, bv, palpha, alphas + (size_t)t * PP);
        // gate partials (split-K x4), sigmoid in context
        tc_gemm<<<dim3(16, 1, 4), 256, SMEM_SZ>>>(Xh + 2560, Xl + 2560, XK,
                                                  BWfb_h, BWfb_l, nullptr, pgatep, EE, EE, HH);
        context_kernel<<<dim3(EE / 256, BB), 256>>>(img, palpha, pgatep, bfb, Xh, Xl);
        emb_kernel<<<(BB * HH) / 256, 256>>>(Wemb, cap, t, Xh, Xl);
        // gates partials (split-K x3), summed + bl in lstm
        tc_gemm<<<dim3(16, 1, 3), 256, SMEM_SZ>>>(Xh, Xl, XK,
                                                  BWcat_h, BWcat_l, nullptr, pgatesp, G4, G4, XK);
        lstm_kernel<<<(BB * HH) / 256, 256>>>(pgatesp, bl, pc, Xh, Xl);
        // preds (no split)
        tc_gemm<<<dim3(VPAD / 128, 1, 1), 256, SMEM_SZ>>>(Xh + 2560, Xl + 2560, XK,
                                                          BWdo_h, BWdo_l, bdo,
                                                          preds + (size_t)t * VV,
                                                          SS * VV, VV, HH);
    }
}

// round 8
// speedup vs baseline: 1.2268x; 1.2268x over previous
#include <cuda_runtime.h>
#include <cuda_bf16.h>
#include <math.h>
#include <stdint.h>

#define BB 128
#define PP 196
#define EE 2048
#define HH 512
#define VV 10000
#define VPAD 10112
#define TT 20
#define SS 19
#define XK 3072
#define G4 2048

typedef __nv_bfloat16 bf16;

// ---------------- device global scratch ----------------
__device__ bf16  g_imgh[(size_t)BB * PP * EE];
__device__ bf16  g_imgl[(size_t)BB * PP * EE];
__device__ float g_Ws[(size_t)BB * PP * HH];
__device__ bf16  g_BWatt_h[HH * EE],  g_BWatt_l[HH * EE];
__device__ bf16  g_BWih_h[HH * EE],   g_BWih_l[HH * EE];
__device__ bf16  g_BWic_h[HH * EE],   g_BWic_l[HH * EE];
__device__ bf16  g_BUatt_h[HH * HH],  g_BUatt_l[HH * HH];
__device__ bf16  g_BWfb_h[EE * HH],   g_BWfb_l[EE * HH];
__device__ bf16  g_BWcat_h[(size_t)G4 * XK], g_BWcat_l[(size_t)G4 * XK];
__device__ bf16  g_BWdo_h[(size_t)VPAD * HH], g_BWdo_l[(size_t)VPAD * HH];
__device__ bf16  g_avgh[BB * EE], g_avgl[BB * EE];
__device__ bf16  g_Xh[BB * XK],   g_Xl[BB * XK];
__device__ bf16  g_Hh[(size_t)SS * BB * HH], g_Hl[(size_t)SS * BB * HH];  // h history
__device__ float g_c[BB * HH];
__device__ float g_alpha[BB * PP];
// split-K partials. g_gatep doubles as h0 partials, g_gatesp as c0 partials.
__device__ float g_qp[8 * BB * HH];
__device__ float g_gatep[8 * BB * EE];
__device__ float g_gatesp[6 * BB * G4];

// ---------------- helpers ----------------
__device__ __forceinline__ uint32_t s2u(const void* p) {
    uint32_t a;
    asm("{ .reg .u64 t; cvta.to.shared.u64 t, %1; cvt.u32.u64 %0, t; }" : "=r"(a) : "l"(p));
    return a;
}
__device__ __forceinline__ void cp16(uint32_t s, const void* g) {
    asm volatile("cp.async.cg.shared.global [%0], [%1], 16;" :: "r"(s), "l"(g) : "memory");
}
__device__ __forceinline__ void cp_commit() { asm volatile("cp.async.commit_group;" ::: "memory"); }
template <int N> __device__ __forceinline__ void cp_wait() {
    asm volatile("cp.async.wait_group %0;" :: "n"(N) : "memory");
}
__device__ __forceinline__ void ldsm4(uint32_t* r, uint32_t addr) {
    asm volatile("ldmatrix.sync.aligned.m8n8.x4.shared.b16 {%0,%1,%2,%3}, [%4];"
                 : "=r"(r[0]), "=r"(r[1]), "=r"(r[2]), "=r"(r[3]) : "r"(addr));
}
__device__ __forceinline__ void mma16816(float* d, const uint32_t* a, const uint32_t* b) {
    asm volatile("mma.sync.aligned.m16n8k16.row.col.f32.bf16.bf16.f32 "
                 "{%0,%1,%2,%3}, {%4,%5,%6,%7}, {%8,%9}, {%0,%1,%2,%3};"
                 : "+f"(d[0]), "+f"(d[1]), "+f"(d[2]), "+f"(d[3])
                 : "r"(a[0]), "r"(a[1]), "r"(a[2]), "r"(a[3]), "r"(b[0]), "r"(b[1]));
}
__device__ __forceinline__ float ex2f(float x) { float r; asm("ex2.approx.f32 %0,%1;" : "=f"(r) : "f"(x)); return r; }
__device__ __forceinline__ float rcpf(float x) { float r; asm("rcp.approx.f32 %0,%1;" : "=f"(r) : "f"(x)); return r; }
__device__ __forceinline__ float tanh_fast(float x) {
    float ax = fabsf(x);
    float e  = ex2f(ax * -2.8853900817779268f);
    float r  = (1.0f - e) * rcpf(1.0f + e);
    return copysignf(r, x);
}
__device__ __forceinline__ void split2(float v, bf16* ph, bf16* pl) {
    bf16 h = __float2bfloat16(v);
    *ph = h;
    *pl = __float2bfloat16(v - __bfloat162float(h));
}

// ---------------- split-bf16 HMMA GEMM, 4-stage pipeline, split-K via grid.z ----
// C tile base = C + z*gridDim.y*tile_stride + blockIdx.y*tile_stride ;
// row r in tile stored at C[r*ldc + n].  (normal: tile_stride = 128*ldc)
#define TILE_B   10240
#define BUF_B    40960
#define SMEM_SZ  163840

__global__ void __launch_bounds__(256, 1)
tc_gemm(const bf16* __restrict__ Ah, const bf16* __restrict__ Al, int lda,
        const bf16* __restrict__ Bh, const bf16* __restrict__ Bl,
        const float* __restrict__ bias, float* __restrict__ C, int ldc,
        long tile_stride, int Nstore, int K)
{
    extern __shared__ char sm[];
    const int tid = threadIdx.x, lane = tid & 31, wid = tid >> 5;
    const int m0 = blockIdx.y << 7, n0 = blockIdx.x << 7;
    const int wy = wid & 1, wx = wid >> 1;
    const uint32_t sb = s2u(sm);

    const int kc = K / gridDim.z;
    const size_t kofs = (size_t)blockIdx.z * kc * 2;
    C += (size_t)blockIdx.z * gridDim.y * tile_stride + (size_t)blockIdx.y * tile_stride;

    const char* gAh = (const char*)(Ah + (size_t)m0 * lda) + kofs;
    const char* gAl = (const char*)(Al + (size_t)m0 * lda) + kofs;
    const char* gBh = (const char*)(Bh + (size_t)n0 * K) + kofs;
    const char* gBl = (const char*)(Bl + (size_t)n0 * K) + kofs;
    const size_t strA = (size_t)lda * 2, strB = (size_t)K * 2;

    const int arow = lane & 15;
    const int acol = (lane >> 4) << 4;
    const int brow = ((lane >> 4) << 3) + (lane & 7);
    const int bcol = ((lane >> 3) & 1) << 4;
    const uint32_t aoff = (uint32_t)((wy * 64 + arow) * 80 + acol);
    const uint32_t boff = (uint32_t)((wx * 32 + brow) * 80 + bcol);

    float acc[4][4][4] = {};
    const int nk = kc >> 5;

    auto issue = [&](int ch) {
        if (ch < nk) {
            const int k0b = ch << 6;
            const uint32_t s0 = sb + (ch & 3) * BUF_B;
            #pragma unroll
            for (int half = 0; half < 2; half++) {
                int u  = tid + half * 256;
                int r  = u >> 2;
                int sg = (u & 3) << 4;
                uint32_t s = s0 + r * 80 + sg;
                size_t gA = (size_t)r * strA + k0b + sg;
                size_t gB = (size_t)r * strB + k0b + sg;
                cp16(s,              gAh + gA);
                cp16(s + TILE_B,     gAl + gA);
                cp16(s + 2 * TILE_B, gBh + gB);
                cp16(s + 3 * TILE_B, gBl + gB);
            }
        }
        cp_commit();
    };

    issue(0); issue(1); issue(2);

    for (int ch = 0; ch < nk; ch++) {
        cp_wait<2>();
        __syncthreads();
        issue(ch + 3);

        const uint32_t base = sb + (ch & 3) * BUF_B;
        #pragma unroll
        for (int ks = 0; ks < 2; ks++) {
            uint32_t ah[4][4], al[4][4];
            #pragma unroll
            for (int mi = 0; mi < 4; mi++) {
                uint32_t o = aoff + mi * (16 * 80) + ks * 32;
                ldsm4(ah[mi], base + o);
                ldsm4(al[mi], base + TILE_B + o);
            }
            uint32_t bh[2][4], bl[2][4];
            #pragma unroll
            for (int nj = 0; nj < 2; nj++) {
                uint32_t o = boff + nj * (16 * 80) + ks * 32;
                ldsm4(bh[nj], base + 2 * TILE_B + o);
                ldsm4(bl[nj], base + 3 * TILE_B + o);
            }
            #pragma unroll
            for (int mi = 0; mi < 4; mi++) {
                #pragma unroll
                for (int n8 = 0; n8 < 4; n8++) {
                    const uint32_t* pbh = &bh[n8 >> 1][(n8 & 1) << 1];
                    const uint32_t* pbl = &bl[n8 >> 1][(n8 & 1) << 1];
                    mma16816(acc[mi][n8], ah[mi], pbh);
                    mma16816(acc[mi][n8], ah[mi], pbl);
                    mma16816(acc[mi][n8], al[mi], pbh);
                }
            }
        }
    }

    #pragma unroll
    for (int mi = 0; mi < 4; mi++) {
        #pragma unroll
        for (int n8 = 0; n8 < 4; n8++) {
            int rb = wy * 64 + mi * 16 + (lane >> 2);
            int nb = n0 + wx * 32 + n8 * 8 + ((lane & 3) << 1);
            #pragma unroll
            for (int g = 0; g < 2; g++) {
                int r = rb + g * 8;
                #pragma unroll
                for (int j = 0; j < 2; j++) {
                    int n = nb + j;
                    if (n < Nstore) {
                        float v = acc[mi][n8][g * 2 + j];
                        if (bias) v += bias[n];
                        C[(size_t)r * ldc + n] = v;
                    }
                }
            }
        }
    }
}

// ---------------- conversion kernels ----------------
__global__ void split_kernel(const float* __restrict__ src, bf16* __restrict__ dh,
                             bf16* __restrict__ dl, int n)
{
    int i = blockIdx.x * 256 + threadIdx.x;
    if (i < n) split2(src[i], dh + i, dl + i);
}

__global__ void tsplit_kernel(const float* __restrict__ src, bf16* __restrict__ dh,
                              bf16* __restrict__ dl, int Ksrc, int N, int dst_ld, int koff)
{
    __shared__ float t[32][33];
    const int n0 = blockIdx.x << 5, k0 = blockIdx.y << 5;
    #pragma unroll
    for (int j = 0; j < 4; j++) {
        int kk = k0 + threadIdx.y + (j << 3);
        int n  = n0 + threadIdx.x;
        t[threadIdx.y + (j << 3)][threadIdx.x] = (n < N) ? src[(size_t)kk * N + n] : 0.0f;
    }
    __syncthreads();
    #pragma unroll
    for (int j = 0; j < 4; j++) {
        int nn = n0 + threadIdx.y + (j << 3);
        int k  = k0 + threadIdx.x;
        size_t o = (size_t)nn * dst_ld + koff + k;
        split2(t[threadIdx.x][threadIdx.y + (j << 3)], dh + o, dl + o);
    }
}

// ---------------- pointwise / attention kernels ----------------
__global__ void avg_kernel(const float* __restrict__ img,
                           bf16* __restrict__ ah, bf16* __restrict__ al)
{
    int b = blockIdx.y;
    int e = blockIdx.x * 256 + threadIdx.x;
    const float* ib = img + (size_t)b * PP * EE + e;
    float s = 0;
    #pragma unroll 4
    for (int p = 0; p < PP; p++) s += ib[(size_t)p * EE];
    split2(s * (1.0f / PP), ah + b * EE + e, al + b * EE + e);
}

// sum 8 partials for h0/c0, tanh, write c + X h-slice + emb(0)
__global__ void combine_init(const float* __restrict__ hp, const float* __restrict__ cp,
                             const float* __restrict__ bih, const float* __restrict__ bic,
                             const float* __restrict__ Wemb, const int* __restrict__ cap,
                             float* __restrict__ c, bf16* __restrict__ Xh, bf16* __restrict__ Xl)
{
    int i = blockIdx.x * 256 + threadIdx.x;   // B*H
    int b = i >> 9, h = i & 511;
    float sh = bih[h], sc = bic[h];
    #pragma unroll
    for (int z = 0; z < 8; z++) { sh += hp[z * BB * HH + i]; sc += cp[z * BB * HH + i]; }
    c[i] = tanhf(sc);
    size_t o = (size_t)b * XK + 2560 + h;
    split2(tanhf(sh), Xh + o, Xl + o);
    // emb for t=0
    int cw = cap[b * TT + 0];
    size_t oe = (size_t)b * XK + h;
    split2(Wemb[(size_t)cw * HH + h], Xh + oe, Xl + oe);
}

__global__ void __launch_bounds__(256)
attention_kernel(const float* __restrict__ Ws, const float* __restrict__ qp,
                 const float* __restrict__ bU,
                 const float* __restrict__ v_att, const float* __restrict__ bv,
                 float* __restrict__ alpha, float* __restrict__ alpha_out)
{
    __shared__ float qs[HH], vs[HH], es[PP], red[8];
    const int b = blockIdx.x, tid = threadIdx.x;
    const int lane = tid & 31, warp = tid >> 5;

    for (int i = tid; i < HH; i += 256) {
        float s = bU[i];
        #pragma unroll
        for (int z = 0; z < 8; z++) s += qp[z * BB * HH + b * HH + i];
        qs[i] = s;
        vs[i] = v_att[i];
    }
    __syncthreads();

    const float* Wb = Ws + (size_t)b * PP * HH;
    const float bv0 = bv[0];
    for (int p = warp; p < PP; p += 8) {
        const float* row = Wb + (size_t)p * HH;
        float s = 0.0f;
        #pragma unroll
        for (int i = 0; i < HH / 32; i++) {
            int h = lane + 32 * i;
            s += vs[h] * tanh_fast(row[h] + qs[h]);
        }
        #pragma unroll
        for (int o = 16; o; o >>= 1) s += __shfl_xor_sync(0xffffffffu, s, o);
        if (lane == 0) es[p] = s + bv0;
    }
    __syncthreads();

    float m = -1e30f;
    for (int p = tid; p < PP; p += 256) m = fmaxf(m, es[p]);
    #pragma unroll
    for (int o = 16; o; o >>= 1) m = fmaxf(m, __shfl_xor_sync(0xffffffffu, m, o));
    if (lane == 0) red[warp] = m;
    __syncthreads();
    if (warp == 0) {
        float t = (lane < 8) ? red[lane] : -1e30f;
        #pragma unroll
        for (int o = 4; o; o >>= 1) t = fmaxf(t, __shfl_xor_sync(0xffffffffu, t, o));
        if (lane == 0) red[0] = t;
    }
    __syncthreads();
    m = red[0];
    __syncthreads();

    float sum = 0.0f;
    for (int p = tid; p < PP; p += 256) { float ev = expf(es[p] - m); es[p] = ev; sum += ev; }
    #pragma unroll
    for (int o = 16; o; o >>= 1) sum += __shfl_xor_sync(0xffffffffu, sum, o);
    if (lane == 0) red[warp] = sum;
    __syncthreads();
    if (warp == 0) {
        float t = (lane < 8) ? red[lane] : 0.0f;
        #pragma unroll
        for (int o = 4; o; o >>= 1) t += __shfl_xor_sync(0xffffffffu, t, o);
        if (lane == 0) red[0] = t;
    }
    __syncthreads();
    float inv = 1.0f / red[0];
    for (int p = tid; p < PP; p += 256) {
        float a = es[p] * inv;
        alpha[b * PP + p] = a;
        alpha_out[(size_t)b * (SS * PP) + p] = a;
    }
}

__global__ void context_kernel(const float* __restrict__ img, const float* __restrict__ alpha,
                               const float* __restrict__ gatep, const float* __restrict__ bfb,
                               bf16* __restrict__ Xh, bf16* __restrict__ Xl)
{
    __shared__ float al[PP];
    const int b = blockIdx.y;
    const int e = blockIdx.x * 256 + threadIdx.x;
    if (threadIdx.x < PP) al[threadIdx.x] = alpha[b * PP + threadIdx.x];
    __syncthreads();
    const float* ib = img + (size_t)b * PP * EE + e;
    float s0 = 0, s1 = 0, s2 = 0, s3 = 0;
    #pragma unroll 4
    for (int p = 0; p < PP; p += 4) {
        s0 += al[p    ] * ib[(size_t)(p    ) * EE];
        s1 += al[p + 1] * ib[(size_t)(p + 1) * EE];
        s2 += al[p + 2] * ib[(size_t)(p + 2) * EE];
        s3 += al[p + 3] * ib[(size_t)(p + 3) * EE];
    }
    float gs = bfb[e];
    #pragma unroll
    for (int z = 0; z < 8; z++) gs += gatep[(size_t)z * BB * EE + b * EE + e];
    float gate = 1.0f / (1.0f + expf(-gs));
    float v = (s0 + s1 + s2 + s3) * gate;
    size_t o = (size_t)b * XK + HH + e;
    split2(v, Xh + o, Xl + o);
}

// LSTM + h history + emb for next step
__global__ void lstm_kernel(const float* __restrict__ gatesp, const float* __restrict__ bl,
                            float* __restrict__ c, bf16* __restrict__ Xh, bf16* __restrict__ Xl,
                            bf16* __restrict__ Hh, bf16* __restrict__ Hl,
                            const float* __restrict__ Wemb, const int* __restrict__ cap, int t)
{
    int i = blockIdx.x * 256 + threadIdx.x;
    int b = i >> 9, h = i & 511;
    float g[4];
    #pragma unroll
    for (int k = 0; k < 4; k++) {
        int j = k * HH + h;
        float s = bl[j];
        #pragma unroll
        for (int z = 0; z < 6; z++) s += gatesp[(size_t)z * BB * G4 + b * G4 + j];
        g[k] = s;
    }
    float ig = 1.0f / (1.0f + expf(-g[0]));
    float fg = 1.0f / (1.0f + expf(-g[1]));
    float gg = tanhf(g[2]);
    float og = 1.0f / (1.0f + expf(-g[3]));
    float cn = fg * c[i] + ig * gg;
    c[i] = cn;
    float hn = og * tanhf(cn);
    size_t o = (size_t)b * XK + 2560 + h;
    split2(hn, Xh + o, Xl + o);
    size_t oh = (size_t)(t * BB + b) * HH + h;
    split2(hn, Hh + oh, Hl + oh);
    // emb for step t+1 (cap has TT=20 cols; t+1 <= 19 valid)
    int cw = cap[b * TT + (t + 1)];
    size_t oe = (size_t)b * XK + h;
    split2(Wemb[(size_t)cw * HH + h], Xh + oe, Xl + oe);
}

// ---------------- host launch ----------------
extern "C" void kernel_launch(void* const* d_in, const int* in_sizes, int n_in,
                              void* d_out, int out_size)
{
    const float* img   = (const float*)d_in[0];
    const int*   cap   = (const int*)  d_in[1];
    const float* U_att = (const float*)d_in[2];
    const float* bU    = (const float*)d_in[3];
    const float* W_att = (const float*)d_in[4];
    const float* bW    = (const float*)d_in[5];
    const float* v_att = (const float*)d_in[6];
    const float* bv    = (const float*)d_in[7];
    const float* Wih   = (const float*)d_in[8];
    const float* bih   = (const float*)d_in[9];
    const float* Wic   = (const float*)d_in[10];
    const float* bic   = (const float*)d_in[11];
    const float* Wfb   = (const float*)d_in[12];
    const float* bfb   = (const float*)d_in[13];
    const float* Wdo   = (const float*)d_in[14];
    const float* bdo   = (const float*)d_in[15];
    const float* Wemb  = (const float*)d_in[16];
    const float* Wl    = (const float*)d_in[17];
    const float* Ul    = (const float*)d_in[18];
    const float* bl    = (const float*)d_in[19];

    float* preds  = (float*)d_out;
    float* alphas = (float*)d_out + (size_t)BB * SS * VV;

    bf16 *imgh, *imgl, *BWatt_h, *BWatt_l, *BWih_h, *BWih_l, *BWic_h, *BWic_l;
    bf16 *BUatt_h, *BUatt_l, *BWfb_h, *BWfb_l, *BWcat_h, *BWcat_l, *BWdo_h, *BWdo_l;
    bf16 *avgh, *avgl, *Xh, *Xl, *Hh, *Hl;
    float *pWs, *pc, *palpha, *pqp, *pgatep, *pgatesp;
    cudaGetSymbolAddress((void**)&imgh, g_imgh);     cudaGetSymbolAddress((void**)&imgl, g_imgl);
    cudaGetSymbolAddress((void**)&BWatt_h, g_BWatt_h); cudaGetSymbolAddress((void**)&BWatt_l, g_BWatt_l);
    cudaGetSymbolAddress((void**)&BWih_h, g_BWih_h); cudaGetSymbolAddress((void**)&BWih_l, g_BWih_l);
    cudaGetSymbolAddress((void**)&BWic_h, g_BWic_h); cudaGetSymbolAddress((void**)&BWic_l, g_BWic_l);
    cudaGetSymbolAddress((void**)&BUatt_h, g_BUatt_h); cudaGetSymbolAddress((void**)&BUatt_l, g_BUatt_l);
    cudaGetSymbolAddress((void**)&BWfb_h, g_BWfb_h); cudaGetSymbolAddress((void**)&BWfb_l, g_BWfb_l);
    cudaGetSymbolAddress((void**)&BWcat_h, g_BWcat_h); cudaGetSymbolAddress((void**)&BWcat_l, g_BWcat_l);
    cudaGetSymbolAddress((void**)&BWdo_h, g_BWdo_h); cudaGetSymbolAddress((void**)&BWdo_l, g_BWdo_l);
    cudaGetSymbolAddress((void**)&avgh, g_avgh);     cudaGetSymbolAddress((void**)&avgl, g_avgl);
    cudaGetSymbolAddress((void**)&Xh, g_Xh);         cudaGetSymbolAddress((void**)&Xl, g_Xl);
    cudaGetSymbolAddress((void**)&Hh, g_Hh);         cudaGetSymbolAddress((void**)&Hl, g_Hl);
    cudaGetSymbolAddress((void**)&pWs, g_Ws);        cudaGetSymbolAddress((void**)&pc, g_c);
    cudaGetSymbolAddress((void**)&palpha, g_alpha);
    cudaGetSymbolAddress((void**)&pqp, g_qp);
    cudaGetSymbolAddress((void**)&pgatep, g_gatep);
    cudaGetSymbolAddress((void**)&pgatesp, g_gatesp);

    cudaFuncSetAttribute(tc_gemm, cudaFuncAttributeMaxDynamicSharedMemorySize, SMEM_SZ);

    // one-time conversions
    {
        int n = BB * PP * EE;
        split_kernel<<<(n + 255) / 256, 256>>>(img, imgh, imgl, n);
        dim3 blk(32, 8);
        tsplit_kernel<<<dim3(16, 64), blk>>>(W_att, BWatt_h, BWatt_l, EE, HH, EE, 0);
        tsplit_kernel<<<dim3(16, 64), blk>>>(Wih,   BWih_h,  BWih_l,  EE, HH, EE, 0);
        tsplit_kernel<<<dim3(16, 64), blk>>>(Wic,   BWic_h,  BWic_l,  EE, HH, EE, 0);
        tsplit_kernel<<<dim3(16, 16), blk>>>(U_att, BUatt_h, BUatt_l, HH, HH, HH, 0);
        tsplit_kernel<<<dim3(64, 16), blk>>>(Wfb,   BWfb_h,  BWfb_l,  HH, EE, HH, 0);
        tsplit_kernel<<<dim3(64, 80), blk>>>(Wl,    BWcat_h, BWcat_l, 2560, G4, XK, 0);
        tsplit_kernel<<<dim3(64, 16), blk>>>(Ul,    BWcat_h, BWcat_l, HH,   G4, XK, 2560);
        tsplit_kernel<<<dim3(VPAD / 32, 16), blk>>>(Wdo, BWdo_h, BWdo_l, HH, VV, HH, 0);
    }

    // init: avg -> h0/c0 partials (split-K x8) -> combine (+ emb(0))
    avg_kernel<<<dim3(EE / 256, BB), 256>>>(img, avgh, avgl);
    tc_gemm<<<dim3(4, 1, 8), 256, SMEM_SZ>>>(avgh, avgl, EE, BWih_h, BWih_l,
                                             nullptr, pgatep, HH, (long)128 * HH, HH, EE);
    tc_gemm<<<dim3(4, 1, 8), 256, SMEM_SZ>>>(avgh, avgl, EE, BWic_h, BWic_l,
                                             nullptr, pgatesp, HH, (long)128 * HH, HH, EE);
    combine_init<<<(BB * HH) / 256, 256>>>(pgatep, pgatesp, bih, bic, Wemb, cap, pc, Xh, Xl);

    // W_s = img @ W_att + bW
    tc_gemm<<<dim3(4, 196, 1), 256, SMEM_SZ>>>(imgh, imgl, EE, BWatt_h, BWatt_l,
                                               bW, pWs, HH, (long)128 * HH, HH, EE);

    for (int t = 0; t < SS; t++) {
        // q partials (split-K x8)
        tc_gemm<<<dim3(4, 1, 8), 256, SMEM_SZ>>>(Xh + 2560, Xl + 2560, XK,
                                                 BUatt_h, BUatt_l, nullptr, pqp,
                                                 HH, (long)128 * HH, HH, HH);
        attention_kernel<<<BB, 256>>>(pWs, pqp, bU, v_att, bv, palpha, alphas + (size_t)t * PP);
        // gate partials (split-K x8)
        tc_gemm<<<dim3(16, 1, 8), 256, SMEM_SZ>>>(Xh + 2560, Xl + 2560, XK,
                                                  BWfb_h, BWfb_l, nullptr, pgatep,
                                                  EE, (long)128 * EE, EE, HH);
        context_kernel<<<dim3(EE / 256, BB), 256>>>(img, palpha, pgatep, bfb, Xh, Xl);
        // gates partials (split-K x6)
        tc_gemm<<<dim3(16, 1, 6), 256, SMEM_SZ>>>(Xh, Xl, XK,
                                                  BWcat_h, BWcat_l, nullptr, pgatesp,
                                                  G4, (long)128 * G4, G4, XK);
        lstm_kernel<<<(BB * HH) / 256, 256>>>(pgatesp, bl, pc, Xh, Xl, Hh, Hl, Wemb, cap, t);
    }

    // batched preds for all 19 steps: [SS*BB, VPAD] = H_hist @ Wdo^T + bdo
    tc_gemm<<<dim3(VPAD / 128, SS, 1), 256, SMEM_SZ>>>(Hh, Hl, HH, BWdo_h, BWdo_l,
                                                       bdo, preds, SS * VV, (long)VV,
                                                       VV, HH);
}